// round 14
// baseline (speedup 1.0000x reference)
#include <cuda_runtime.h>
#include <math.h>

#define NB 16
#define NF 200
#define TT 96000
#define CS 2048
#define NCS 47          // ceil(96000/2048), ragged last chunk
#define FULLMASK 0xFFFFFFFFu
#define DPI 3.141592653589793
#define TWO_PI 6.283185307179586
#define TWO_PI_F 6.2831854820251465f
#define SEG 2000
#define NSEG 48         // 48*2000 = 96000
#define FT 512          // k_fir tile (2 outputs/thread)
#define NFT 188         // ceil(96000/512)

// XLA AlgebraicSimplifier folds x/const -> x * (1/const), reciprocal rounded to f32.
#define RINV_SR   ((float)(1.0/48000.0))
#define RINV_NYQ  ((float)(1.0/24000.0))
#define RINV_DEC  ((float)(1.0/(2.0*DPI*0.87)))

// ---------------- static device scratch ----------------
__device__ float   g_f0u  [NB*TT];
__device__ float   g_sig0 [NB*TT];
__device__ float   g_alpha[NB*TT];
__device__ float   g_noise[NB*TT];
__device__ float   g_x    [NB*TT];   // Apre after k_convIir
__device__ float   g_y    [NB*TT];   // carry-free y0 after k_convIir
__device__ double4 g_coef [NB*(NF-1)];
__device__ float   g_ir[127];
__device__ float   g_wm[16];     // wm[0]=win[15]; wm[m]=win[15+m]/(pi*m)
__device__ double  g_csum[NB*NCS];
__device__ int     g_flag[NB*NCS];   // lookback flags (zeroed each launch)
__device__ int     g_done;           // convIir completion counter (zeroed each launch)
__device__ float   g_segA[NB*NSEG];
__device__ float   g_segX[NB*NSEG];
__device__ float   g_carry[NB*NSEG];
// piecewise-linear MLP LUT: 64 sorted breakpoints, 65 (A,B) segments
__device__ float   g_bp[64];
__device__ float   g_A [65];
__device__ float   g_B [65];

// ---------------- fast accurate f32 sine (args in [0, ~1e5)) ----------------
__device__ __forceinline__ void fsincos(float x, float* s, float* c){
    float n = rintf(__fmul_rn(x, 0.63661975f));
    int q = (int)n;
    float r = fmaf(n, -1.5707963705062866f, x);
    r = fmaf(n, 4.37113883e-8f, r);
    float r2 = __fmul_rn(r, r);
    float si = fmaf(r2, -1.9515296e-4f, 8.3321609e-3f);
    si = fmaf(r2, si, -1.6666654e-1f);
    float sp = fmaf(__fmul_rn(r2, r), si, r);
    float ci = fmaf(r2, 2.443315711e-5f, -1.388731625e-3f);
    ci = fmaf(r2, ci, 4.166664568e-2f);
    ci = fmaf(r2, ci, -0.5f);
    float cp = fmaf(r2, ci, 1.0f);
    float ss = (q & 1) ? cp : sp;
    float cc = (q & 1) ? sp : cp;
    if (q & 2) ss = -ss;
    if ((q + 1) & 2) cc = -cc;
    *s = ss; *c = cc;
}

// ---------------- helpers ----------------
__device__ __forceinline__ int sgnf(float x){ return (x > 0.f) - (x < 0.f); }

__device__ __forceinline__ float endslope(float d0, float d1){
    float d = __fmul_rn(0.5f, __fadd_rn(__fmul_rn(3.0f, d0), -d1));
    if (sgnf(d) != sgnf(d0)) d = 0.0f;
    if ((sgnf(d0) != sgnf(d1)) && (fabsf(d) > __fmul_rn(3.0f, fabsf(d0))))
        d = __fmul_rn(3.0f, d0);
    return d;
}

__device__ __forceinline__ float eval_f0u_c(const double4* __restrict__ cc, int t){
    int i = t / 480;
    if (i > NF-2) i = NF-2;
    int rem = t - i * 480;
    double u = (double)rem * (1.0/480.0);
    u = (double)(float)u;                 // reference casts u to f32
    double4 c = cc[i];
    double f = ((c.w * u + c.z) * u + c.y) * u + c.x;
    return (float)f;
}

// ---------------- kernel 1: constants + cubic coeffs + MLP segment LUT + flag reset ----------------
__global__ void k_setup(const float* __restrict__ f0,
                        const float* __restrict__ w1,
                        const float* __restrict__ b1,
                        const float* __restrict__ w2,
                        const float* __restrict__ b2){
    int blk = blockIdx.x, tid = threadIdx.x;
    if (blk == NB){
        __shared__ double warpsum[8];
        __shared__ double nrm_s;
        for (int i = tid; i < NB*NCS; i += 256) g_flag[i] = 0;
        if (tid == 255) g_done = 0;
        double val = 0.0, v = 0.0;
        if (tid < 127){
            double t = -0.5 + (double)tid / 126.0;
            double chirp = sin(50.0 * t * t);
            double win = 0.5 * (1.0 - cos(2.0 * DPI * (double)tid / 127.0));
            val = chirp * win;
            v = val * val;
        }
        for (int d = 16; d > 0; d >>= 1) v += __shfl_down_sync(FULLMASK, v, d);
        if ((tid & 31) == 0) warpsum[tid >> 5] = v;
        __syncthreads();
        if (tid == 0){
            double s = 0.0;
            for (int w = 0; w < 8; w++) s += warpsum[w];
            nrm_s = sqrt(s) + 1e-8;
        }
        __syncthreads();
        if (tid < 127) g_ir[tid] = (float)(val / nrm_s);
        if (tid < 16){
            double nf = (double)tid;
            double win = 0.54 + 0.46 * cos(2.0 * DPI * nf / 31.0);
            g_wm[tid] = (tid == 0) ? (float)win : (float)(win / (DPI * nf));
        }
        return;
    }
    if (blk == NB + 1){
        __shared__ float sw1[64], sb1[64], sw2[64], sbp[64], ssort[64];
        __shared__ int   srank[64];
        if (tid < 64){ sw1[tid] = w1[tid]; sb1[tid] = b1[tid]; sw2[tid] = w2[tid]; }
        __syncthreads();
        if (tid < 64){
            float w = sw1[tid];
            float bp = (w != 0.0f) ? (-sb1[tid] / w) : __int_as_float(0x7f800000);
            sbp[tid] = bp;
        }
        __syncthreads();
        if (tid < 64){
            float bpi = sbp[tid];
            int r = 0;
            #pragma unroll 8
            for (int j = 0; j < 64; j++){
                float bj = sbp[j];
                r += (bj < bpi) || (bj == bpi && j < tid);
            }
            srank[tid] = r;
            ssort[r] = bpi;
        }
        __syncthreads();
        if (tid < 64) g_bp[tid] = ssort[tid];
        if (tid <= 64){
            double A = 0.0, B = (double)b2[0];
            for (int o = 0; o < 64; o++){
                float w = sw1[o];
                double sig;
                if (w > 0.0f)      sig = (tid > srank[o])  ? 1.0 : 0.2;
                else if (w < 0.0f) sig = (tid <= srank[o]) ? 1.0 : 0.2;
                else               sig = (sb1[o] >= 0.0f)  ? 1.0 : 0.2;
                A += (double)sw2[o] * (double)w * sig;
                B += (double)sw2[o] * (double)sb1[o] * sig;
            }
            g_A[tid] = (float)A;
            g_B[tid] = (float)B;
        }
        return;
    }
    __shared__ float sy[NF], sdel[NF-1], sd[NF];
    int b = blk;
    if (tid < NF) sy[tid] = f0[b*NF + tid];
    __syncthreads();
    if (tid < NF-1) sdel[tid] = __fadd_rn(sy[tid+1], -sy[tid]);
    __syncthreads();
    if (tid >= 1 && tid <= NF-2){
        float dl = sdel[tid-1], dr = sdel[tid];
        float v = 0.0f;
        if (__fmul_rn(dl, dr) > 0.0f)
            v = __fdiv_rn(__fmul_rn(__fmul_rn(2.0f, dl), dr),
                          __fadd_rn(__fadd_rn(dl, dr), 1e-30f));
        sd[tid] = v;
    }
    if (tid == 0)    sd[0]    = endslope(sdel[0], sdel[1]);
    if (tid == NF-1) sd[NF-1] = endslope(sdel[NF-2], sdel[NF-3]);
    __syncthreads();
    if (tid < NF-1){
        double y0 = (double)sy[tid], y1 = (double)sy[tid+1];
        double d0 = (double)sd[tid], d1 = (double)sd[tid+1];
        double4 c;
        c.x = y0;
        c.y = d0;
        c.z = 3.0*(y1 - y0) - 2.0*d0 - d1;
        c.w = 2.0*(y0 - y1) + d0 + d1;
        g_coef[b*(NF-1) + tid] = c;
    }
}

// ---------------- kernel 2: fused f0u eval + decoupled-lookback scan + source ----------------
__global__ void __launch_bounds__(256) k_phase(const float* __restrict__ ip,
                                               const float* __restrict__ n1,
                                               const float* __restrict__ n2){
    __shared__ float s_bp[64], s_A[65], s_B[65];
    __shared__ double s_sc[8];
    __shared__ double s_red[2];
    int b = blockIdx.y, c = blockIdx.x, tid = threadIdx.x;
    if (tid < 64) s_bp[tid] = g_bp[tid];
    if (tid < 65){ s_A[tid] = g_A[tid]; s_B[tid] = g_B[tid]; }

    const double4* cc = g_coef + b*(NF-1);
    float ip0 = ip[b];
    int base = c * CS + tid * 8;
    bool val8 = (base + 8 <= TT);
    float fv[8], locf[8];
    float run = 0.0f;
    if (val8){
        #pragma unroll
        for (int j = 0; j < 8; j++){
            float f = eval_f0u_c(cc, base + j);
            fv[j] = f;
            float inc = __fmul_rn(f, RINV_SR);
            if (base + j == 0) inc = __fadd_rn(inc, ip0);
            run = __fadd_rn(run, inc);
            locf[j] = run;
        }
        *(float4*)(g_f0u + b*TT + base)     = make_float4(fv[0], fv[1], fv[2], fv[3]);
        *(float4*)(g_f0u + b*TT + base + 4) = make_float4(fv[4], fv[5], fv[6], fv[7]);
    } else {
        #pragma unroll
        for (int j = 0; j < 8; j++){ fv[j] = 0.0f; locf[j] = 0.0f; }
    }
    double s = (double)run;
    double incv = s;
    int lane = tid & 31, w = tid >> 5;
    #pragma unroll
    for (int d = 1; d < 32; d <<= 1){
        double p = __shfl_up_sync(FULLMASK, incv, d);
        if (lane >= d) incv += p;
    }
    if (lane == 31) s_sc[w] = incv;
    __syncthreads();
    if (tid == 0){
        double run2 = 0.0;
        for (int i = 0; i < 8; i++){ double t = s_sc[i]; s_sc[i] = run2; run2 += t; }
        g_csum[b*NCS + c] = run2;
        __threadfence();
        atomicExch(&g_flag[b*NCS + c], 1);
    }
    double v = 0.0;
    if (tid < c){                     // c <= 46
        volatile int* f = (volatile int*)&g_flag[b*NCS + tid];
        while (*f == 0) __nanosleep(40);
        __threadfence();
        v = g_csum[b*NCS + tid];
    }
    if (tid < 64)
        for (int d = 16; d > 0; d >>= 1) v += __shfl_down_sync(FULLMASK, v, d);
    if (tid == 0)  s_red[0] = v;
    if (tid == 32) s_red[1] = v;
    __syncthreads();
    if (!val8) return;
    double base_d = (s_red[0] + s_red[1]) + s_sc[w] + (incv - s);  // >= 0
    float rbase = (float)(base_d - trunc(base_d));

    #pragma unroll
    for (int j = 0; j < 8; j++){
        int t = base + j;
        int idx = b*TT + t;
        float cumf = __fadd_rn(rbase, locf[j]);
        float frac = cumf - floorf(cumf);
        float phase = __fmul_rn(frac, TWO_PI_F);
        float f0u = fv[j];
        float voiced = (f0u > 1.0f) ? 1.0f : 0.0f;
        float safe = fmaxf(f0u, 1e-5f);
        float Nn = floorf(__fdiv_rn(24000.0f, safe));   // exact div: N boundary-critical

        float sig = 0.0f;
        float alpha = 0.0f;
        float fn;
        if (voiced > 0.5f){
            float half = __fmul_rn(0.5f, phase);
            float sh, ch;
            fsincos(half, &sh, &ch);
            float den = sh;
            if (fabsf(den) < 1e-6f) den = (den >= 0.0f) ? 1e-6f : -1e-6f;
            float a1 = __fmul_rn(Nn, half);
            float sN, cN;
            fsincos(a1, &sN, &cN);
            float s2 = fmaf(sN, ch, __fmul_rn(cN, sh));  // sin((N+1)*half)
            float harm = __fdiv_rn(__fmul_rn(sN, s2), den);
            float amp = 0.14142136f * rsqrtf(fmaxf(Nn, 1.0f));  // 0.1*sqrt(2/N)
            sig = harm * amp;

            float x = __log2f(fmaf(__fmul_rn(f0u, RINV_NYQ), 10.0f, 1.0f));
            int kk = (s_bp[31] < x) ? 32 : 0;
            kk += (s_bp[kk+15] < x) ? 16 : 0;
            kk += (s_bp[kk+ 7] < x) ?  8 : 0;
            kk += (s_bp[kk+ 3] < x) ?  4 : 0;
            kk += (s_bp[kk+ 1] < x) ?  2 : 0;
            kk += (s_bp[kk   ] < x) ?  1 : 0;
            float z = fmaf(s_A[kk], x, s_B[kk]);
            float sg = 1.0f / (1.0f + __expf(-z));
            alpha = sg * 0.98f;

            float dec = __expf(-__fmul_rn(phase, RINV_DEC));
            fn = (n1[idx] * dec) * 0.003f;
        } else {
            fn = n2[idx] * (float)(0.1 / 3.0);
        }

        g_sig0[idx]  = sig;
        g_alpha[idx] = alpha;
        g_noise[idx] = fn;
    }
}

// ---------------- kernel 3: fused 127-tap conv + IIR scan + last-block carry chain ----------------
__global__ void __launch_bounds__(256) k_convIir(float* __restrict__ out, int out_size){
    __shared__ __align__(16) float s_s[SEG + 136];
    __shared__ __align__(16) float s_ir[128];
    __shared__ float sA[32], sX[32], sPA[32], sPX[32];
    __shared__ int s_last;
    int b = blockIdx.y, seg = blockIdx.x;
    int tid = threadIdx.x, lane = tid & 31, wid = tid >> 5;
    const float* sigb = g_sig0 + b*TT;
    const float* alb  = g_alpha + b*TT;
    float* yb = g_y + b*TT;
    float* pb = g_x + b*TT;
    if (tid < 128) s_ir[tid] = (tid < 127) ? g_ir[tid] : 0.0f;
    int off = seg * SEG;
    for (int j = tid; j < SEG + 136; j += 256){
        int g = off - 63 + j;
        s_s[j] = (g >= 0 && g < TT) ? sigb[g] : 0.0f;
    }
    __syncthreads();
    int o = tid * 8;
    bool valid = (o + 8 <= SEG);     // threads 0..249
    float a0=0.f,a1=0.f,a2=0.f,a3=0.f,a4=0.f,a5=0.f,a6=0.f,a7=0.f;
    float4 aL = make_float4(1.f,1.f,1.f,1.f), aH = aL;
    float4 xL = make_float4(0.f,0.f,0.f,0.f), xH = xL;
    if (valid){
        float4 wva = *(const float4*)&s_s[o];
        float4 wvb = *(const float4*)&s_s[o + 4];
        float w0 = wva.x, w1 = wva.y, w2 = wva.z, w3 = wva.w;
        float w4 = wvb.x, w5 = wvb.y, w6 = wvb.z, w7 = wvb.w;
        #pragma unroll
        for (int k = 0; k < 128; k += 4){
            float4 ir = *(const float4*)&s_ir[k];
            float4 nx = *(const float4*)&s_s[o + k + 8];
            a0=fmaf(w0,ir.x,a0); a1=fmaf(w1,ir.x,a1); a2=fmaf(w2,ir.x,a2); a3=fmaf(w3,ir.x,a3);
            a4=fmaf(w4,ir.x,a4); a5=fmaf(w5,ir.x,a5); a6=fmaf(w6,ir.x,a6); a7=fmaf(w7,ir.x,a7);
            a0=fmaf(w1,ir.y,a0); a1=fmaf(w2,ir.y,a1); a2=fmaf(w3,ir.y,a2); a3=fmaf(w4,ir.y,a3);
            a4=fmaf(w5,ir.y,a4); a5=fmaf(w6,ir.y,a5); a6=fmaf(w7,ir.y,a6); a7=fmaf(nx.x,ir.y,a7);
            a0=fmaf(w2,ir.z,a0); a1=fmaf(w3,ir.z,a1); a2=fmaf(w4,ir.z,a2); a3=fmaf(w5,ir.z,a3);
            a4=fmaf(w6,ir.z,a4); a5=fmaf(w7,ir.z,a5); a6=fmaf(nx.x,ir.z,a6); a7=fmaf(nx.y,ir.z,a7);
            a0=fmaf(w3,ir.w,a0); a1=fmaf(w4,ir.w,a1); a2=fmaf(w5,ir.w,a2); a3=fmaf(w6,ir.w,a3);
            a4=fmaf(w7,ir.w,a4); a5=fmaf(nx.x,ir.w,a5); a6=fmaf(nx.y,ir.w,a6); a7=fmaf(nx.z,ir.w,a7);
            w0=w4; w1=w5; w2=w6; w3=w7;
            w4=nx.x; w5=nx.y; w6=nx.z; w7=nx.w;
        }
        aL = *(const float4*)(alb + off + o);
        aH = *(const float4*)(alb + off + o + 4);
        xL = make_float4((1.0f-aL.x)*a0, (1.0f-aL.y)*a1, (1.0f-aL.z)*a2, (1.0f-aL.w)*a3);
        xH = make_float4((1.0f-aH.x)*a4, (1.0f-aH.y)*a5, (1.0f-aH.z)*a6, (1.0f-aH.w)*a7);
    }
    float A = aL.x, X = xL.x;
    X = fmaf(aL.y, X, xL.y); A = aL.y * A;
    X = fmaf(aL.z, X, xL.z); A = aL.z * A;
    X = fmaf(aL.w, X, xL.w); A = aL.w * A;
    X = fmaf(aH.x, X, xH.x); A = aH.x * A;
    X = fmaf(aH.y, X, xH.y); A = aH.y * A;
    X = fmaf(aH.z, X, xH.z); A = aH.z * A;
    X = fmaf(aH.w, X, xH.w); A = aH.w * A;
    float Ai = A, Xi = X;
    #pragma unroll
    for (int d = 1; d < 32; d <<= 1){
        float ap = __shfl_up_sync(FULLMASK, Ai, d);
        float xp = __shfl_up_sync(FULLMASK, Xi, d);
        if (lane >= d){ Xi = fmaf(Ai, xp, Xi); Ai *= ap; }
    }
    if (lane == 31){ sA[wid] = Ai; sX[wid] = Xi; }
    __syncthreads();
    if (wid == 0){
        float wa2 = sA[lane], wx2 = sX[lane];
        #pragma unroll
        for (int d = 1; d < 32; d <<= 1){
            float ap = __shfl_up_sync(FULLMASK, wa2, d);
            float xp = __shfl_up_sync(FULLMASK, wx2, d);
            if (lane >= d){ wx2 = fmaf(wa2, xp, wx2); wa2 *= ap; }
        }
        sPA[lane] = wa2; sPX[lane] = wx2;
        if (lane == 7){
            g_segA[b*NSEG + seg] = wa2;
            g_segX[b*NSEG + seg] = wx2;
            __threadfence();
        }
    }
    __syncthreads();
    float eA = __shfl_up_sync(FULLMASK, Ai, 1);
    float eX = __shfl_up_sync(FULLMASK, Xi, 1);
    if (lane == 0){ eA = 1.0f; eX = 0.0f; }
    float wA = 1.0f, wX = 0.0f;
    if (wid > 0){ wA = sPA[wid-1]; wX = sPX[wid-1]; }
    float xin = fmaf(eA, wX, eX);
    float Ain = eA * wA;
    float y1 = fmaf(aL.x, xin, xL.x);  float p1 = aL.x * Ain;
    float y2 = fmaf(aL.y, y1, xL.y);   float p2 = aL.y * p1;
    float y3 = fmaf(aL.z, y2, xL.z);   float p3 = aL.z * p2;
    float y4 = fmaf(aL.w, y3, xL.w);   float p4 = aL.w * p3;
    float y5 = fmaf(aH.x, y4, xH.x);   float p5 = aH.x * p4;
    float y6 = fmaf(aH.y, y5, xH.y);   float p6 = aH.y * p5;
    float y7 = fmaf(aH.z, y6, xH.z);   float p7 = aH.z * p6;
    float y8 = fmaf(aH.w, y7, xH.w);   float p8 = aH.w * p7;
    if (valid){
        *(float4*)(yb + off + o)     = make_float4(y1, y2, y3, y4);
        *(float4*)(yb + off + o + 4) = make_float4(y5, y6, y7, y8);
        *(float4*)(pb + off + o)     = make_float4(p1, p2, p3, p4);
        *(float4*)(pb + off + o + 4) = make_float4(p5, p6, p7, p8);
    }
    if (tid == 0){
        __threadfence();
        int old = atomicAdd(&g_done, 1);
        s_last = (old == NB*NSEG - 1) ? 1 : 0;
    }
    __syncthreads();
    if (s_last && tid < NB){
        __threadfence();
        float carry = 0.0f;
        int bb = tid;
        for (int s2 = 0; s2 < NSEG; s2++){
            g_carry[bb*NSEG + s2] = carry;
            carry = fmaf(g_segA[bb*NSEG + s2], carry, g_segX[bb*NSEG + s2]);
        }
        if (out_size >= NB*TT + NB) out[NB*TT + bb] = carry;  // new_state
    }
}

// ---------------- kernel 4: sinc LP/HP FIR + tanh (merged loop, 2 outputs/thread) ----------------
__global__ void __launch_bounds__(256) k_fir(const float* __restrict__ cw,
                                             const float* __restrict__ cb,
                                             const float* __restrict__ lw,
                                             float* __restrict__ out){
    __shared__ __align__(8) float2 s_yn[FT + 30];
    __shared__ float s_wm[16], s_cr[NSEG];
    int b = blockIdx.y, tb = blockIdx.x * FT, tid = threadIdx.x;
    const float* yb = g_y + b * TT;
    const float* pb = g_x + b * TT;   // Apre
    const float* nb = g_noise + b * TT;
    if (tid < 16) s_wm[tid] = g_wm[tid];
    if (tid >= 64 && tid < 64 + NSEG) s_cr[tid - 64] = g_carry[b*NSEG + (tid - 64)];
    __syncthreads();
    for (int j = tid; j < FT + 30; j += 256){
        int g = tb - 30 + j;
        float yv = 0.0f, nv = 0.0f;
        if (g >= 0 && g < TT){
            int seg = g / SEG;
            yv = fmaf(pb[g], s_cr[seg], yb[g]);   // y = y0 + Apre*carry
            nv = nb[g];
        }
        s_yn[j] = make_float2(yv, nv);
    }
    __syncthreads();
    float cw0 = cw[0], cb0 = cb[0], lw0 = lw[0];
    const float PI_F = 3.14159274101257324f;
    #pragma unroll
    for (int r = 0; r < 2; r++){
        int li = tid + r * 256;      // local output index in tile
        int t = tb + li;
        if (t >= TT) continue;
        float f0u = g_f0u[b*TT + t];
        float cz = fmaf(cw0, __fmul_rn(f0u, RINV_NYQ), cb0);
        float cv = 1.0f / (1.0f + __expf(-cz));
        float theta = __fmul_rn(PI_F, cv);
        float s1, c1;
        fsincos(theta, &s1, &c1);
        float twoc = __fadd_rn(c1, c1);
        // merged single-pass: Chebyshev recurrence + normalization sums + taps
        float lum0 = __fmul_rn(cv, s_wm[0]);
        float2 cen = s_yn[li + 15];
        float accY = __fmul_rn(lum0, cen.x);
        float accN = __fmul_rn(lum0, cen.y);
        float se = 0.0f, so = 0.0f;
        float sm1 = 0.0f, sm = s1;
        #pragma unroll
        for (int m = 1; m < 16; m++){
            float l = __fmul_rn(sm, s_wm[m]);
            if (m & 1) so += l; else se += l;
            float2 um = s_yn[li + 15 - m];
            float2 up = s_yn[li + 15 + m];
            accY = fmaf(l, __fadd_rn(um.x, up.x), accY);
            accN = fmaf(l, __fadd_rn(um.y, up.y), accN);
            float sn = fmaf(twoc, sm, -sm1);
            sm1 = sm; sm = sn;
        }
        float suml = lum0 + 2.0f*(se + so);
        float sumh = (s_wm[0] - lum0) - 2.0f*se + 2.0f*so;
        float rl = __fdividef(1.0f, suml + 1e-8f);
        float rh = __fdividef(1.0f, sumh + 1e-8f);
        float e = accY * rl + (s_wm[0] * cen.y - accN) * rh;
        out[b*TT + t] = tanhf(lw0 * e);
    }
}

// ---------------- launcher ----------------
extern "C" void kernel_launch(void* const* d_in, const int* in_sizes, int n_in,
                              void* d_out, int out_size){
    const float* f0 = (const float*)d_in[0];
    const float* ip = (const float*)d_in[1];
    const float* n1 = (const float*)d_in[2];
    const float* n2 = (const float*)d_in[3];
    const float* w1 = (const float*)d_in[4];
    const float* b1 = (const float*)d_in[5];
    const float* w2 = (const float*)d_in[6];
    const float* b2 = (const float*)d_in[7];
    const float* cw = (const float*)d_in[8];
    const float* cb = (const float*)d_in[9];
    const float* lw = (const float*)d_in[10];
    float* out = (float*)d_out;

    k_setup<<<NB + 2, 256>>>(f0, w1, b1, w2, b2);
    k_phase<<<dim3(NCS, NB), 256>>>(ip, n1, n2);
    k_convIir<<<dim3(NSEG, NB), 256>>>(out, out_size);
    k_fir<<<dim3(NFT, NB), 256>>>(cw, cb, lw, out);
}

// round 16
// speedup vs baseline: 1.0314x; 1.0314x over previous
#include <cuda_runtime.h>
#include <math.h>

#define NB 16
#define NF 200
#define TT 96000
#define CS 2048
#define NCS 47          // ceil(96000/2048), ragged last chunk
#define FULLMASK 0xFFFFFFFFu
#define DPI 3.141592653589793
#define TWO_PI 6.283185307179586
#define TWO_PI_F 6.2831854820251465f
#define SEG 2000
#define NSEG 48         // 48*2000 = 96000
#define FT 512          // k_fir tile (2 outputs/thread)
#define NFT 188         // ceil(96000/512)

// XLA AlgebraicSimplifier folds x/const -> x * (1/const), reciprocal rounded to f32.
#define RINV_SR   ((float)(1.0/48000.0))
#define RINV_NYQ  ((float)(1.0/24000.0))
#define RINV_DEC  ((float)(1.0/(2.0*DPI*0.87)))

typedef unsigned long long u64;

// ---------------- compile-time Hamming/sinc window constants ----------------
// wm[0]=win[15]=1.0; wm[m]=win[15+m]/(pi*m). Computed via constexpr Taylor cos
// (<=1e-16 abs err for |x|<=3.1) -> f32 identical to the double libm path.
constexpr double ccos_t(double x){
    double x2 = x*x, t = 1.0, s = 1.0;
    for (int k = 1; k <= 15; k++){ t *= -x2 / (double)((2*k-1)*(2*k)); s += t; }
    return s;
}
constexpr float wmf(int m){
    return (float)((0.54 + 0.46 * ccos_t(2.0*DPI*(double)m/31.0)) / (DPI*(double)m));
}
__device__ constexpr float WMT[16] = {
    1.0f,    wmf(1),  wmf(2),  wmf(3),  wmf(4),  wmf(5),  wmf(6),  wmf(7),
    wmf(8),  wmf(9),  wmf(10), wmf(11), wmf(12), wmf(13), wmf(14), wmf(15)
};

// ---------------- packed f32x2 helpers (each half correctly rounded) ----------------
__device__ __forceinline__ u64 pk2(float lo, float hi){
    u64 r; asm("mov.b64 %0, {%1, %2};" : "=l"(r) : "f"(lo), "f"(hi)); return r;
}
__device__ __forceinline__ void unpk2(u64 v, float* lo, float* hi){
    asm("mov.b64 {%0, %1}, %2;" : "=f"(*lo), "=f"(*hi) : "l"(v));
}
__device__ __forceinline__ u64 add2(u64 a, u64 b){
    u64 r; asm("add.rn.f32x2 %0, %1, %2;" : "=l"(r) : "l"(a), "l"(b)); return r;
}
__device__ __forceinline__ u64 mul2(u64 a, u64 b){
    u64 r; asm("mul.rn.f32x2 %0, %1, %2;" : "=l"(r) : "l"(a), "l"(b)); return r;
}
__device__ __forceinline__ void fma2a(u64& d, u64 a, u64 b){
    asm("fma.rn.f32x2 %0, %1, %2, %0;" : "+l"(d) : "l"(a), "l"(b));
}

// ---------------- static device scratch ----------------
__device__ float   g_f0u  [NB*TT];
__device__ float   g_sig0 [NB*TT];
__device__ float   g_alpha[NB*TT];
__device__ float   g_noise[NB*TT];
__device__ float   g_x    [NB*TT];   // Apre after k_convIir
__device__ float   g_y    [NB*TT];   // carry-free y0 after k_convIir
__device__ double4 g_coef [NB*(NF-1)];
__device__ float   g_ir[127];
__device__ double  g_csum[NB*NCS];
__device__ int     g_flag[NB*NCS];   // lookback flags (zeroed each launch)
__device__ int     g_done;           // convIir completion counter (zeroed each launch)
__device__ float   g_segA[NB*NSEG];
__device__ float   g_segX[NB*NSEG];
__device__ float   g_carry[NB*NSEG];
// piecewise-linear MLP LUT: 64 sorted breakpoints, 65 (A,B) segments
__device__ float   g_bp[64];
__device__ float   g_A [65];
__device__ float   g_B [65];

// ---------------- fast accurate f32 sine (args in [0, ~1e5)) ----------------
__device__ __forceinline__ void fsincos(float x, float* s, float* c){
    float n = rintf(__fmul_rn(x, 0.63661975f));
    int q = (int)n;
    float r = fmaf(n, -1.5707963705062866f, x);
    r = fmaf(n, 4.37113883e-8f, r);
    float r2 = __fmul_rn(r, r);
    float si = fmaf(r2, -1.9515296e-4f, 8.3321609e-3f);
    si = fmaf(r2, si, -1.6666654e-1f);
    float sp = fmaf(__fmul_rn(r2, r), si, r);
    float ci = fmaf(r2, 2.443315711e-5f, -1.388731625e-3f);
    ci = fmaf(r2, ci, 4.166664568e-2f);
    ci = fmaf(r2, ci, -0.5f);
    float cp = fmaf(r2, ci, 1.0f);
    float ss = (q & 1) ? cp : sp;
    float cc = (q & 1) ? sp : cp;
    if (q & 2) ss = -ss;
    if ((q + 1) & 2) cc = -cc;
    *s = ss; *c = cc;
}

// ---------------- helpers ----------------
__device__ __forceinline__ int sgnf(float x){ return (x > 0.f) - (x < 0.f); }

__device__ __forceinline__ float endslope(float d0, float d1){
    float d = __fmul_rn(0.5f, __fadd_rn(__fmul_rn(3.0f, d0), -d1));
    if (sgnf(d) != sgnf(d0)) d = 0.0f;
    if ((sgnf(d0) != sgnf(d1)) && (fabsf(d) > __fmul_rn(3.0f, fabsf(d0))))
        d = __fmul_rn(3.0f, d0);
    return d;
}

__device__ __forceinline__ float eval_f0u_c(const double4* __restrict__ cc, int t){
    int i = t / 480;
    if (i > NF-2) i = NF-2;
    int rem = t - i * 480;
    double u = (double)rem * (1.0/480.0);
    u = (double)(float)u;                 // reference casts u to f32
    double4 c = cc[i];
    double f = ((c.w * u + c.z) * u + c.y) * u + c.x;
    return (float)f;
}

// ---------------- kernel 1: constants + cubic coeffs + MLP segment LUT + flag reset ----------------
__global__ void k_setup(const float* __restrict__ f0,
                        const float* __restrict__ w1,
                        const float* __restrict__ b1,
                        const float* __restrict__ w2,
                        const float* __restrict__ b2){
    int blk = blockIdx.x, tid = threadIdx.x;
    if (blk == NB){
        __shared__ double warpsum[8];
        __shared__ double nrm_s;
        for (int i = tid; i < NB*NCS; i += 256) g_flag[i] = 0;
        if (tid == 255) g_done = 0;
        double val = 0.0, v = 0.0;
        if (tid < 127){
            double t = -0.5 + (double)tid / 126.0;
            double chirp = sin(50.0 * t * t);
            double win = 0.5 * (1.0 - cos(2.0 * DPI * (double)tid / 127.0));
            val = chirp * win;
            v = val * val;
        }
        for (int d = 16; d > 0; d >>= 1) v += __shfl_down_sync(FULLMASK, v, d);
        if ((tid & 31) == 0) warpsum[tid >> 5] = v;
        __syncthreads();
        if (tid == 0){
            double s = 0.0;
            for (int w = 0; w < 8; w++) s += warpsum[w];
            nrm_s = sqrt(s) + 1e-8;
        }
        __syncthreads();
        if (tid < 127) g_ir[tid] = (float)(val / nrm_s);
        return;
    }
    if (blk == NB + 1){
        __shared__ float sw1[64], sb1[64], sw2[64], sbp[64], ssort[64];
        __shared__ int   srank[64];
        if (tid < 64){ sw1[tid] = w1[tid]; sb1[tid] = b1[tid]; sw2[tid] = w2[tid]; }
        __syncthreads();
        if (tid < 64){
            float w = sw1[tid];
            float bp = (w != 0.0f) ? (-sb1[tid] / w) : __int_as_float(0x7f800000);
            sbp[tid] = bp;
        }
        __syncthreads();
        if (tid < 64){
            float bpi = sbp[tid];
            int r = 0;
            #pragma unroll 8
            for (int j = 0; j < 64; j++){
                float bj = sbp[j];
                r += (bj < bpi) || (bj == bpi && j < tid);
            }
            srank[tid] = r;
            ssort[r] = bpi;
        }
        __syncthreads();
        if (tid < 64) g_bp[tid] = ssort[tid];
        if (tid <= 64){
            double A = 0.0, B = (double)b2[0];
            for (int o = 0; o < 64; o++){
                float w = sw1[o];
                double sig;
                if (w > 0.0f)      sig = (tid > srank[o])  ? 1.0 : 0.2;
                else if (w < 0.0f) sig = (tid <= srank[o]) ? 1.0 : 0.2;
                else               sig = (sb1[o] >= 0.0f)  ? 1.0 : 0.2;
                A += (double)sw2[o] * (double)w * sig;
                B += (double)sw2[o] * (double)sb1[o] * sig;
            }
            g_A[tid] = (float)A;
            g_B[tid] = (float)B;
        }
        return;
    }
    __shared__ float sy[NF], sdel[NF-1], sd[NF];
    int b = blk;
    if (tid < NF) sy[tid] = f0[b*NF + tid];
    __syncthreads();
    if (tid < NF-1) sdel[tid] = __fadd_rn(sy[tid+1], -sy[tid]);
    __syncthreads();
    if (tid >= 1 && tid <= NF-2){
        float dl = sdel[tid-1], dr = sdel[tid];
        float v = 0.0f;
        if (__fmul_rn(dl, dr) > 0.0f)
            v = __fdiv_rn(__fmul_rn(__fmul_rn(2.0f, dl), dr),
                          __fadd_rn(__fadd_rn(dl, dr), 1e-30f));
        sd[tid] = v;
    }
    if (tid == 0)    sd[0]    = endslope(sdel[0], sdel[1]);
    if (tid == NF-1) sd[NF-1] = endslope(sdel[NF-2], sdel[NF-3]);
    __syncthreads();
    if (tid < NF-1){
        double y0 = (double)sy[tid], y1 = (double)sy[tid+1];
        double d0 = (double)sd[tid], d1 = (double)sd[tid+1];
        double4 c;
        c.x = y0;
        c.y = d0;
        c.z = 3.0*(y1 - y0) - 2.0*d0 - d1;
        c.w = 2.0*(y0 - y1) + d0 + d1;
        g_coef[b*(NF-1) + tid] = c;
    }
}

// ---------------- kernel 2: fused f0u eval + decoupled-lookback scan + source ----------------
__global__ void __launch_bounds__(256) k_phase(const float* __restrict__ ip,
                                               const float* __restrict__ n1,
                                               const float* __restrict__ n2){
    __shared__ float s_bp[64], s_A[65], s_B[65];
    __shared__ double s_sc[8];
    __shared__ double s_red[2];
    int b = blockIdx.y, c = blockIdx.x, tid = threadIdx.x;
    if (tid < 64) s_bp[tid] = g_bp[tid];
    if (tid < 65){ s_A[tid] = g_A[tid]; s_B[tid] = g_B[tid]; }

    const double4* cc = g_coef + b*(NF-1);
    float ip0 = ip[b];
    int base = c * CS + tid * 8;
    bool val8 = (base + 8 <= TT);
    float fv[8], locf[8];
    float run = 0.0f;
    if (val8){
        #pragma unroll
        for (int j = 0; j < 8; j++){
            float f = eval_f0u_c(cc, base + j);
            fv[j] = f;
            float inc = __fmul_rn(f, RINV_SR);
            if (base + j == 0) inc = __fadd_rn(inc, ip0);
            run = __fadd_rn(run, inc);
            locf[j] = run;
        }
        *(float4*)(g_f0u + b*TT + base)     = make_float4(fv[0], fv[1], fv[2], fv[3]);
        *(float4*)(g_f0u + b*TT + base + 4) = make_float4(fv[4], fv[5], fv[6], fv[7]);
    } else {
        #pragma unroll
        for (int j = 0; j < 8; j++){ fv[j] = 0.0f; locf[j] = 0.0f; }
    }
    double s = (double)run;
    double incv = s;
    int lane = tid & 31, w = tid >> 5;
    #pragma unroll
    for (int d = 1; d < 32; d <<= 1){
        double p = __shfl_up_sync(FULLMASK, incv, d);
        if (lane >= d) incv += p;
    }
    if (lane == 31) s_sc[w] = incv;
    __syncthreads();
    if (tid == 0){
        double run2 = 0.0;
        for (int i = 0; i < 8; i++){ double t = s_sc[i]; s_sc[i] = run2; run2 += t; }
        g_csum[b*NCS + c] = run2;
        __threadfence();
        atomicExch(&g_flag[b*NCS + c], 1);
    }
    double v = 0.0;
    if (tid < c){                     // c <= 46
        volatile int* f = (volatile int*)&g_flag[b*NCS + tid];
        while (*f == 0) __nanosleep(40);
        __threadfence();
        v = g_csum[b*NCS + tid];
    }
    if (tid < 64)
        for (int d = 16; d > 0; d >>= 1) v += __shfl_down_sync(FULLMASK, v, d);
    if (tid == 0)  s_red[0] = v;
    if (tid == 32) s_red[1] = v;
    __syncthreads();
    if (!val8) return;
    double base_d = (s_red[0] + s_red[1]) + s_sc[w] + (incv - s);  // >= 0
    float rbase = (float)(base_d - trunc(base_d));

    #pragma unroll
    for (int j = 0; j < 8; j++){
        int t = base + j;
        int idx = b*TT + t;
        float cumf = __fadd_rn(rbase, locf[j]);
        float frac = cumf - floorf(cumf);
        float phase = __fmul_rn(frac, TWO_PI_F);
        float f0u = fv[j];
        float voiced = (f0u > 1.0f) ? 1.0f : 0.0f;
        float safe = fmaxf(f0u, 1e-5f);
        float Nn = floorf(__fdiv_rn(24000.0f, safe));   // exact div: N boundary-critical

        float sig = 0.0f;
        float alpha = 0.0f;
        float fn;
        if (voiced > 0.5f){
            float half = __fmul_rn(0.5f, phase);
            float sh, ch;
            fsincos(half, &sh, &ch);
            float den = sh;
            if (fabsf(den) < 1e-6f) den = (den >= 0.0f) ? 1e-6f : -1e-6f;
            float a1 = __fmul_rn(Nn, half);
            float sN, cN;
            fsincos(a1, &sN, &cN);
            float s2 = fmaf(sN, ch, __fmul_rn(cN, sh));  // sin((N+1)*half)
            float harm = __fdiv_rn(__fmul_rn(sN, s2), den);
            float amp = 0.14142136f * rsqrtf(fmaxf(Nn, 1.0f));  // 0.1*sqrt(2/N)
            sig = harm * amp;

            float x = __log2f(fmaf(__fmul_rn(f0u, RINV_NYQ), 10.0f, 1.0f));
            int kk = (s_bp[31] < x) ? 32 : 0;
            kk += (s_bp[kk+15] < x) ? 16 : 0;
            kk += (s_bp[kk+ 7] < x) ?  8 : 0;
            kk += (s_bp[kk+ 3] < x) ?  4 : 0;
            kk += (s_bp[kk+ 1] < x) ?  2 : 0;
            kk += (s_bp[kk   ] < x) ?  1 : 0;
            float z = fmaf(s_A[kk], x, s_B[kk]);
            float sg = 1.0f / (1.0f + __expf(-z));
            alpha = sg * 0.98f;

            float dec = __expf(-__fmul_rn(phase, RINV_DEC));
            fn = (n1[idx] * dec) * 0.003f;
        } else {
            fn = n2[idx] * (float)(0.1 / 3.0);
        }

        g_sig0[idx]  = sig;
        g_alpha[idx] = alpha;
        g_noise[idx] = fn;
    }
}

// ---------------- kernel 3: fused 127-tap conv + IIR scan + last-block carry chain ----------------
__global__ void __launch_bounds__(256) k_convIir(float* __restrict__ out, int out_size){
    __shared__ __align__(16) float s_s[SEG + 136];
    __shared__ __align__(16) float s_ir[128];
    __shared__ float sA[32], sX[32], sPA[32], sPX[32];
    __shared__ int s_last;
    int b = blockIdx.y, seg = blockIdx.x;
    int tid = threadIdx.x, lane = tid & 31, wid = tid >> 5;
    const float* sigb = g_sig0 + b*TT;
    const float* alb  = g_alpha + b*TT;
    float* yb = g_y + b*TT;
    float* pb = g_x + b*TT;
    if (tid < 128) s_ir[tid] = (tid < 127) ? g_ir[tid] : 0.0f;
    int off = seg * SEG;
    for (int j = tid; j < SEG + 136; j += 256){
        int g = off - 63 + j;
        s_s[j] = (g >= 0 && g < TT) ? sigb[g] : 0.0f;
    }
    __syncthreads();
    int o = tid * 8;
    bool valid = (o + 8 <= SEG);     // threads 0..249
    float a0=0.f,a1=0.f,a2=0.f,a3=0.f,a4=0.f,a5=0.f,a6=0.f,a7=0.f;
    float4 aL = make_float4(1.f,1.f,1.f,1.f), aH = aL;
    float4 xL = make_float4(0.f,0.f,0.f,0.f), xH = xL;
    if (valid){
        float4 wva = *(const float4*)&s_s[o];
        float4 wvb = *(const float4*)&s_s[o + 4];
        float w0 = wva.x, w1 = wva.y, w2 = wva.z, w3 = wva.w;
        float w4 = wvb.x, w5 = wvb.y, w6 = wvb.z, w7 = wvb.w;
        #pragma unroll
        for (int k = 0; k < 128; k += 4){
            float4 ir = *(const float4*)&s_ir[k];
            float4 nx = *(const float4*)&s_s[o + k + 8];
            a0=fmaf(w0,ir.x,a0); a1=fmaf(w1,ir.x,a1); a2=fmaf(w2,ir.x,a2); a3=fmaf(w3,ir.x,a3);
            a4=fmaf(w4,ir.x,a4); a5=fmaf(w5,ir.x,a5); a6=fmaf(w6,ir.x,a6); a7=fmaf(w7,ir.x,a7);
            a0=fmaf(w1,ir.y,a0); a1=fmaf(w2,ir.y,a1); a2=fmaf(w3,ir.y,a2); a3=fmaf(w4,ir.y,a3);
            a4=fmaf(w5,ir.y,a4); a5=fmaf(w6,ir.y,a5); a6=fmaf(w7,ir.y,a6); a7=fmaf(nx.x,ir.y,a7);
            a0=fmaf(w2,ir.z,a0); a1=fmaf(w3,ir.z,a1); a2=fmaf(w4,ir.z,a2); a3=fmaf(w5,ir.z,a3);
            a4=fmaf(w6,ir.z,a4); a5=fmaf(w7,ir.z,a5); a6=fmaf(nx.x,ir.z,a6); a7=fmaf(nx.y,ir.z,a7);
            a0=fmaf(w3,ir.w,a0); a1=fmaf(w4,ir.w,a1); a2=fmaf(w5,ir.w,a2); a3=fmaf(w6,ir.w,a3);
            a4=fmaf(w7,ir.w,a4); a5=fmaf(nx.x,ir.w,a5); a6=fmaf(nx.y,ir.w,a6); a7=fmaf(nx.z,ir.w,a7);
            w0=w4; w1=w5; w2=w6; w3=w7;
            w4=nx.x; w5=nx.y; w6=nx.z; w7=nx.w;
        }
        aL = *(const float4*)(alb + off + o);
        aH = *(const float4*)(alb + off + o + 4);
        xL = make_float4((1.0f-aL.x)*a0, (1.0f-aL.y)*a1, (1.0f-aL.z)*a2, (1.0f-aL.w)*a3);
        xH = make_float4((1.0f-aH.x)*a4, (1.0f-aH.y)*a5, (1.0f-aH.z)*a6, (1.0f-aH.w)*a7);
    }
    float A = aL.x, X = xL.x;
    X = fmaf(aL.y, X, xL.y); A = aL.y * A;
    X = fmaf(aL.z, X, xL.z); A = aL.z * A;
    X = fmaf(aL.w, X, xL.w); A = aL.w * A;
    X = fmaf(aH.x, X, xH.x); A = aH.x * A;
    X = fmaf(aH.y, X, xH.y); A = aH.y * A;
    X = fmaf(aH.z, X, xH.z); A = aH.z * A;
    X = fmaf(aH.w, X, xH.w); A = aH.w * A;
    float Ai = A, Xi = X;
    #pragma unroll
    for (int d = 1; d < 32; d <<= 1){
        float ap = __shfl_up_sync(FULLMASK, Ai, d);
        float xp = __shfl_up_sync(FULLMASK, Xi, d);
        if (lane >= d){ Xi = fmaf(Ai, xp, Xi); Ai *= ap; }
    }
    if (lane == 31){ sA[wid] = Ai; sX[wid] = Xi; }
    __syncthreads();
    if (wid == 0){
        float wa2 = sA[lane], wx2 = sX[lane];
        #pragma unroll
        for (int d = 1; d < 32; d <<= 1){
            float ap = __shfl_up_sync(FULLMASK, wa2, d);
            float xp = __shfl_up_sync(FULLMASK, wx2, d);
            if (lane >= d){ wx2 = fmaf(wa2, xp, wx2); wa2 *= ap; }
        }
        sPA[lane] = wa2; sPX[lane] = wx2;
        if (lane == 7){
            g_segA[b*NSEG + seg] = wa2;
            g_segX[b*NSEG + seg] = wx2;
            __threadfence();
        }
    }
    __syncthreads();
    float eA = __shfl_up_sync(FULLMASK, Ai, 1);
    float eX = __shfl_up_sync(FULLMASK, Xi, 1);
    if (lane == 0){ eA = 1.0f; eX = 0.0f; }
    float wA = 1.0f, wX = 0.0f;
    if (wid > 0){ wA = sPA[wid-1]; wX = sPX[wid-1]; }
    float xin = fmaf(eA, wX, eX);
    float Ain = eA * wA;
    float y1 = fmaf(aL.x, xin, xL.x);  float p1 = aL.x * Ain;
    float y2 = fmaf(aL.y, y1, xL.y);   float p2 = aL.y * p1;
    float y3 = fmaf(aL.z, y2, xL.z);   float p3 = aL.z * p2;
    float y4 = fmaf(aL.w, y3, xL.w);   float p4 = aL.w * p3;
    float y5 = fmaf(aH.x, y4, xH.x);   float p5 = aH.x * p4;
    float y6 = fmaf(aH.y, y5, xH.y);   float p6 = aH.y * p5;
    float y7 = fmaf(aH.z, y6, xH.z);   float p7 = aH.z * p6;
    float y8 = fmaf(aH.w, y7, xH.w);   float p8 = aH.w * p7;
    if (valid){
        *(float4*)(yb + off + o)     = make_float4(y1, y2, y3, y4);
        *(float4*)(yb + off + o + 4) = make_float4(y5, y6, y7, y8);
        *(float4*)(pb + off + o)     = make_float4(p1, p2, p3, p4);
        *(float4*)(pb + off + o + 4) = make_float4(p5, p6, p7, p8);
    }
    if (tid == 0){
        __threadfence();
        int old = atomicAdd(&g_done, 1);
        s_last = (old == NB*NSEG - 1) ? 1 : 0;
    }
    __syncthreads();
    if (s_last && tid < NB){
        __threadfence();
        float carry = 0.0f;
        int bb = tid;
        for (int s2 = 0; s2 < NSEG; s2++){
            g_carry[bb*NSEG + s2] = carry;
            carry = fmaf(g_segA[bb*NSEG + s2], carry, g_segX[bb*NSEG + s2]);
        }
        if (out_size >= NB*TT + NB) out[NB*TT + bb] = carry;  // new_state
    }
}

// ---------------- kernel 4: sinc LP/HP FIR + tanh (packed f32x2 taps, imm window) ----------------
__global__ void __launch_bounds__(256) k_fir(const float* __restrict__ cw,
                                             const float* __restrict__ cb,
                                             const float* __restrict__ lw,
                                             float* __restrict__ out){
    __shared__ __align__(8) float2 s_yn[FT + 30];
    __shared__ float s_cr[NSEG];
    int b = blockIdx.y, tb = blockIdx.x * FT, tid = threadIdx.x;
    const float* yb = g_y + b * TT;
    const float* pb = g_x + b * TT;   // Apre
    const float* nb = g_noise + b * TT;
    if (tid >= 64 && tid < 64 + NSEG) s_cr[tid - 64] = g_carry[b*NSEG + (tid - 64)];
    __syncthreads();
    for (int j = tid; j < FT + 30; j += 256){
        int g = tb - 30 + j;
        float yv = 0.0f, nv = 0.0f;
        if (g >= 0 && g < TT){
            int seg = (int)__umulhi((unsigned)g, 2147484u);   // g / 2000, exact for g < 96000
            yv = fmaf(pb[g], s_cr[seg], yb[g]);   // y = y0 + Apre*carry
            nv = nb[g];
        }
        s_yn[j] = make_float2(yv, nv);
    }
    __syncthreads();
    float cw0 = cw[0], cb0 = cb[0], lw0 = lw[0];
    const float PI_F = 3.14159274101257324f;
    #pragma unroll
    for (int r = 0; r < 2; r++){
        int li = tid + r * 256;      // local output index in tile
        int t = tb + li;
        if (t >= TT) continue;
        float f0u = g_f0u[b*TT + t];
        float cz = fmaf(cw0, __fmul_rn(f0u, RINV_NYQ), cb0);
        float cv = __fdividef(1.0f, 1.0f + __expf(-cz));
        float theta = __fmul_rn(PI_F, cv);
        float s1, c1;
        __sincosf(theta, &s1, &c1);      // theta in (0,pi): MUFU accuracy ~1e-6
        float twoc = __fadd_rn(c1, c1);
        // packed accumulators (accY, accN) in one f32x2 register pair
        float2 cen = s_yn[li + 15];
        u64 cen2 = *(const u64*)&s_yn[li + 15];
        u64 acc = mul2(cen2, pk2(cv, cv));        // lum0 = cv * WM[0] = cv
        float se = 0.0f, so = 0.0f;
        float sm1 = 0.0f, sm = s1;
        #pragma unroll
        for (int m = 1; m < 16; m++){
            float l = __fmul_rn(sm, WMT[m]);      // FMUL with immediate
            if (m & 1) so += l; else se += l;
            u64 um = *(const u64*)&s_yn[li + 15 - m];
            u64 up = *(const u64*)&s_yn[li + 15 + m];
            fma2a(acc, add2(um, up), pk2(l, l));  // both halves correctly rounded
            float sn = fmaf(twoc, sm, -sm1);
            sm1 = sm; sm = sn;
        }
        float accY, accN;
        unpk2(acc, &accY, &accN);
        float suml = cv + 2.0f*(se + so);
        float sumh = (1.0f - cv) - 2.0f*se + 2.0f*so;
        float rl = __fdividef(1.0f, suml + 1e-8f);
        float rh = __fdividef(1.0f, sumh + 1e-8f);
        float e = accY * rl + (cen.y - accN) * rh;   // wm0*cen.y = cen.y
        out[b*TT + t] = tanhf(lw0 * e);
    }
}

// ---------------- launcher ----------------
extern "C" void kernel_launch(void* const* d_in, const int* in_sizes, int n_in,
                              void* d_out, int out_size){
    const float* f0 = (const float*)d_in[0];
    const float* ip = (const float*)d_in[1];
    const float* n1 = (const float*)d_in[2];
    const float* n2 = (const float*)d_in[3];
    const float* w1 = (const float*)d_in[4];
    const float* b1 = (const float*)d_in[5];
    const float* w2 = (const float*)d_in[6];
    const float* b2 = (const float*)d_in[7];
    const float* cw = (const float*)d_in[8];
    const float* cb = (const float*)d_in[9];
    const float* lw = (const float*)d_in[10];
    float* out = (float*)d_out;

    k_setup<<<NB + 2, 256>>>(f0, w1, b1, w2, b2);
    k_phase<<<dim3(NCS, NB), 256>>>(ip, n1, n2);
    k_convIir<<<dim3(NSEG, NB), 256>>>(out, out_size);
    k_fir<<<dim3(NFT, NB), 256>>>(cw, cb, lw, out);
}

// round 17
// speedup vs baseline: 1.1157x; 1.0818x over previous
#include <cuda_runtime.h>
#include <math.h>

#define NB 16
#define NF 200
#define TT 96000
#define CS 2048
#define NCS 47          // ceil(96000/2048), ragged last chunk
#define FULLMASK 0xFFFFFFFFu
#define DPI 3.141592653589793
#define TWO_PI 6.283185307179586
#define TWO_PI_F 6.2831854820251465f
#define SEG 2000
#define NSEG 48         // 48*2000 = 96000
#define FT 512          // k_fir tile (2 outputs/thread)
#define NFT 188         // ceil(96000/512)

// XLA AlgebraicSimplifier folds x/const -> x * (1/const), reciprocal rounded to f32.
#define RINV_SR   ((float)(1.0/48000.0))
#define RINV_NYQ  ((float)(1.0/24000.0))
#define RINV_DEC  ((float)(1.0/(2.0*DPI*0.87)))

typedef unsigned long long u64;

// ---------------- compile-time Hamming/sinc window constants ----------------
constexpr double ccos_t(double x){
    double x2 = x*x, t = 1.0, s = 1.0;
    for (int k = 1; k <= 15; k++){ t *= -x2 / (double)((2*k-1)*(2*k)); s += t; }
    return s;
}
constexpr float wmf(int m){
    return (float)((0.54 + 0.46 * ccos_t(2.0*DPI*(double)m/31.0)) / (DPI*(double)m));
}
__device__ constexpr float WMT[16] = {
    1.0f,    wmf(1),  wmf(2),  wmf(3),  wmf(4),  wmf(5),  wmf(6),  wmf(7),
    wmf(8),  wmf(9),  wmf(10), wmf(11), wmf(12), wmf(13), wmf(14), wmf(15)
};

// ---------------- packed f32x2 helpers (each half correctly rounded) ----------------
__device__ __forceinline__ u64 pk2(float lo, float hi){
    u64 r; asm("mov.b64 %0, {%1, %2};" : "=l"(r) : "f"(lo), "f"(hi)); return r;
}
__device__ __forceinline__ void unpk2(u64 v, float* lo, float* hi){
    asm("mov.b64 {%0, %1}, %2;" : "=f"(*lo), "=f"(*hi) : "l"(v));
}
__device__ __forceinline__ u64 add2(u64 a, u64 b){
    u64 r; asm("add.rn.f32x2 %0, %1, %2;" : "=l"(r) : "l"(a), "l"(b)); return r;
}
__device__ __forceinline__ u64 mul2(u64 a, u64 b){
    u64 r; asm("mul.rn.f32x2 %0, %1, %2;" : "=l"(r) : "l"(a), "l"(b)); return r;
}
__device__ __forceinline__ void fma2a(u64& d, u64 a, u64 b){
    asm("fma.rn.f32x2 %0, %1, %2, %0;" : "+l"(d) : "l"(a), "l"(b));
}

// ---------------- static device scratch ----------------
__device__ float   g_f0u  [NB*TT];
__device__ float   g_sig0 [NB*TT];
__device__ float   g_alpha[NB*TT];
__device__ float   g_noise[NB*TT];
__device__ float   g_x    [NB*TT];   // Apre after k_convIir
__device__ float   g_y    [NB*TT];   // carry-free y0 after k_convIir
__device__ double4 g_coef [NB*(NF-1)];
__device__ float   g_ir[127];
__device__ double  g_csum[NB*NCS];
__device__ int     g_flag[NB*NCS];   // lookback flags (zeroed each launch)
__device__ int     g_done;           // convIir completion counter (zeroed each launch)
__device__ float   g_segA[NB*NSEG];
__device__ float   g_segX[NB*NSEG];
__device__ float   g_carry[NB*NSEG];
// piecewise-linear MLP LUT: 64 sorted breakpoints, 65 (A,B) segments
__device__ float   g_bp[64];
__device__ float   g_A [65];
__device__ float   g_B [65];

// ---------------- fast accurate f32 sin/cos (args in [0, ~1e5)) ----------------
__device__ __forceinline__ void fsincos(float x, float* s, float* c){
    float n = rintf(__fmul_rn(x, 0.63661975f));
    int q = (int)n;
    float r = fmaf(n, -1.5707963705062866f, x);
    r = fmaf(n, 4.37113883e-8f, r);
    float r2 = __fmul_rn(r, r);
    float si = fmaf(r2, -1.9515296e-4f, 8.3321609e-3f);
    si = fmaf(r2, si, -1.6666654e-1f);
    float sp = fmaf(__fmul_rn(r2, r), si, r);
    float ci = fmaf(r2, 2.443315711e-5f, -1.388731625e-3f);
    ci = fmaf(r2, ci, 4.166664568e-2f);
    ci = fmaf(r2, ci, -0.5f);
    float cp = fmaf(r2, ci, 1.0f);
    float ss = (q & 1) ? cp : sp;
    float cc = (q & 1) ? sp : cp;
    if (q & 2) ss = -ss;
    if ((q + 1) & 2) cc = -cc;
    *s = ss; *c = cc;
}

// ---------------- helpers ----------------
__device__ __forceinline__ int sgnf(float x){ return (x > 0.f) - (x < 0.f); }

__device__ __forceinline__ float endslope(float d0, float d1){
    float d = __fmul_rn(0.5f, __fadd_rn(__fmul_rn(3.0f, d0), -d1));
    if (sgnf(d) != sgnf(d0)) d = 0.0f;
    if ((sgnf(d0) != sgnf(d1)) && (fabsf(d) > __fmul_rn(3.0f, fabsf(d0))))
        d = __fmul_rn(3.0f, d0);
    return d;
}

__device__ __forceinline__ float eval_f0u_c(const double4* __restrict__ cc, int t){
    int i = t / 480;
    if (i > NF-2) i = NF-2;
    int rem = t - i * 480;
    double u = (double)rem * (1.0/480.0);
    u = (double)(float)u;                 // reference casts u to f32
    double4 c = cc[i];
    double f = ((c.w * u + c.z) * u + c.y) * u + c.x;
    return (float)f;
}

// ---------------- kernel 1: constants + cubic coeffs + MLP segment LUT + flag reset ----------------
__global__ void k_setup(const float* __restrict__ f0,
                        const float* __restrict__ w1,
                        const float* __restrict__ b1,
                        const float* __restrict__ w2,
                        const float* __restrict__ b2){
    int blk = blockIdx.x, tid = threadIdx.x;
    if (blk == NB){
        __shared__ double warpsum[8];
        __shared__ double nrm_s;
        for (int i = tid; i < NB*NCS; i += 256) g_flag[i] = 0;
        if (tid == 255) g_done = 0;
        double val = 0.0, v = 0.0;
        if (tid < 127){
            double t = -0.5 + (double)tid / 126.0;
            double chirp = sin(50.0 * t * t);
            double win = 0.5 * (1.0 - cos(2.0 * DPI * (double)tid / 127.0));
            val = chirp * win;
            v = val * val;
        }
        for (int d = 16; d > 0; d >>= 1) v += __shfl_down_sync(FULLMASK, v, d);
        if ((tid & 31) == 0) warpsum[tid >> 5] = v;
        __syncthreads();
        if (tid == 0){
            double s = 0.0;
            for (int w = 0; w < 8; w++) s += warpsum[w];
            nrm_s = sqrt(s) + 1e-8;
        }
        __syncthreads();
        if (tid < 127) g_ir[tid] = (float)(val / nrm_s);
        return;
    }
    if (blk == NB + 1){
        __shared__ float sw1[64], sb1[64], sw2[64], sbp[64], ssort[64];
        __shared__ int   srank[64];
        if (tid < 64){ sw1[tid] = w1[tid]; sb1[tid] = b1[tid]; sw2[tid] = w2[tid]; }
        __syncthreads();
        if (tid < 64){
            float w = sw1[tid];
            float bp = (w != 0.0f) ? (-sb1[tid] / w) : __int_as_float(0x7f800000);
            sbp[tid] = bp;
        }
        __syncthreads();
        if (tid < 64){
            float bpi = sbp[tid];
            int r = 0;
            #pragma unroll 8
            for (int j = 0; j < 64; j++){
                float bj = sbp[j];
                r += (bj < bpi) || (bj == bpi && j < tid);
            }
            srank[tid] = r;
            ssort[r] = bpi;
        }
        __syncthreads();
        if (tid < 64) g_bp[tid] = ssort[tid];
        if (tid <= 64){
            double A = 0.0, B = (double)b2[0];
            for (int o = 0; o < 64; o++){
                float w = sw1[o];
                double sig;
                if (w > 0.0f)      sig = (tid > srank[o])  ? 1.0 : 0.2;
                else if (w < 0.0f) sig = (tid <= srank[o]) ? 1.0 : 0.2;
                else               sig = (sb1[o] >= 0.0f)  ? 1.0 : 0.2;
                A += (double)sw2[o] * (double)w * sig;
                B += (double)sw2[o] * (double)sb1[o] * sig;
            }
            g_A[tid] = (float)A;
            g_B[tid] = (float)B;
        }
        return;
    }
    __shared__ float sy[NF], sdel[NF-1], sd[NF];
    int b = blk;
    if (tid < NF) sy[tid] = f0[b*NF + tid];
    __syncthreads();
    if (tid < NF-1) sdel[tid] = __fadd_rn(sy[tid+1], -sy[tid]);
    __syncthreads();
    if (tid >= 1 && tid <= NF-2){
        float dl = sdel[tid-1], dr = sdel[tid];
        float v = 0.0f;
        if (__fmul_rn(dl, dr) > 0.0f)
            v = __fdiv_rn(__fmul_rn(__fmul_rn(2.0f, dl), dr),
                          __fadd_rn(__fadd_rn(dl, dr), 1e-30f));
        sd[tid] = v;
    }
    if (tid == 0)    sd[0]    = endslope(sdel[0], sdel[1]);
    if (tid == NF-1) sd[NF-1] = endslope(sdel[NF-2], sdel[NF-3]);
    __syncthreads();
    if (tid < NF-1){
        double y0 = (double)sy[tid], y1 = (double)sy[tid+1];
        double d0 = (double)sd[tid], d1 = (double)sd[tid+1];
        double4 c;
        c.x = y0;
        c.y = d0;
        c.z = 3.0*(y1 - y0) - 2.0*d0 - d1;
        c.w = 2.0*(y0 - y1) + d0 + d1;
        g_coef[b*(NF-1) + tid] = c;
    }
}

// ---------------- kernel 2: fused f0u eval + decoupled-lookback scan + source ----------------
__global__ void __launch_bounds__(256) k_phase(const float* __restrict__ ip,
                                               const float* __restrict__ n1,
                                               const float* __restrict__ n2){
    __shared__ float s_bp[64], s_A[65], s_B[65];
    __shared__ double s_sc[8];
    __shared__ double s_red[2];
    int b = blockIdx.y, c = blockIdx.x, tid = threadIdx.x;
    if (tid < 64) s_bp[tid] = g_bp[tid];
    if (tid < 65){ s_A[tid] = g_A[tid]; s_B[tid] = g_B[tid]; }

    const double4* cc = g_coef + b*(NF-1);
    float ip0 = ip[b];
    int base = c * CS + tid * 8;
    bool val8 = (base + 8 <= TT);
    float fv[8], locf[8];
    float n1v[8], n2v[8];
    float run = 0.0f;
    if (val8){
        // batched vector loads of both noise streams (MLP >= 4)
        *(float4*)&n1v[0] = *(const float4*)(n1 + b*TT + base);
        *(float4*)&n1v[4] = *(const float4*)(n1 + b*TT + base + 4);
        *(float4*)&n2v[0] = *(const float4*)(n2 + b*TT + base);
        *(float4*)&n2v[4] = *(const float4*)(n2 + b*TT + base + 4);
        #pragma unroll
        for (int j = 0; j < 8; j++){
            float f = eval_f0u_c(cc, base + j);
            fv[j] = f;
            float inc = __fmul_rn(f, RINV_SR);
            if (base + j == 0) inc = __fadd_rn(inc, ip0);
            run = __fadd_rn(run, inc);
            locf[j] = run;
        }
        *(float4*)(g_f0u + b*TT + base)     = make_float4(fv[0], fv[1], fv[2], fv[3]);
        *(float4*)(g_f0u + b*TT + base + 4) = make_float4(fv[4], fv[5], fv[6], fv[7]);
    } else {
        #pragma unroll
        for (int j = 0; j < 8; j++){ fv[j] = 0.0f; locf[j] = 0.0f; }
    }
    double s = (double)run;
    double incv = s;
    int lane = tid & 31, w = tid >> 5;
    #pragma unroll
    for (int d = 1; d < 32; d <<= 1){
        double p = __shfl_up_sync(FULLMASK, incv, d);
        if (lane >= d) incv += p;
    }
    if (lane == 31) s_sc[w] = incv;
    __syncthreads();
    if (tid == 0){
        double run2 = 0.0;
        for (int i = 0; i < 8; i++){ double t = s_sc[i]; s_sc[i] = run2; run2 += t; }
        g_csum[b*NCS + c] = run2;
        __threadfence();
        atomicExch(&g_flag[b*NCS + c], 1);
    }
    double v = 0.0;
    if (tid < c){                     // c <= 46
        volatile int* f = (volatile int*)&g_flag[b*NCS + tid];
        while (*f == 0) __nanosleep(40);
        __threadfence();
        v = g_csum[b*NCS + tid];
    }
    if (tid < 64)
        for (int d = 16; d > 0; d >>= 1) v += __shfl_down_sync(FULLMASK, v, d);
    if (tid == 0)  s_red[0] = v;
    if (tid == 32) s_red[1] = v;
    __syncthreads();
    if (!val8) return;
    double base_d = (s_red[0] + s_red[1]) + s_sc[w] + (incv - s);  // >= 0
    float rbase = (float)(base_d - trunc(base_d));

    float sigv[8], alv[8], fnv[8];
    #pragma unroll
    for (int j = 0; j < 8; j++){
        float cumf = __fadd_rn(rbase, locf[j]);
        float frac = cumf - floorf(cumf);
        float phase = __fmul_rn(frac, TWO_PI_F);
        float f0u = fv[j];
        float voiced = (f0u > 1.0f) ? 1.0f : 0.0f;
        float safe = fmaxf(f0u, 1e-5f);
        float Nn = floorf(__fdiv_rn(24000.0f, safe));   // exact div: N boundary-critical

        float sig = 0.0f;
        float alpha = 0.0f;
        float fn;
        if (voiced > 0.5f){
            float half = __fmul_rn(0.5f, phase);
            float sh, ch;
            fsincos(half, &sh, &ch);
            float den = sh;
            if (fabsf(den) < 1e-6f) den = (den >= 0.0f) ? 1e-6f : -1e-6f;
            float a1 = __fmul_rn(Nn, half);
            float sN, cN;
            fsincos(a1, &sN, &cN);
            float s2 = fmaf(sN, ch, __fmul_rn(cN, sh));  // sin((N+1)*half)
            float harm = __fdiv_rn(__fmul_rn(sN, s2), den);
            float amp = 0.14142136f * rsqrtf(fmaxf(Nn, 1.0f));  // 0.1*sqrt(2/N)
            sig = harm * amp;

            float x = __log2f(fmaf(__fmul_rn(f0u, RINV_NYQ), 10.0f, 1.0f));
            int kk = (s_bp[31] < x) ? 32 : 0;
            kk += (s_bp[kk+15] < x) ? 16 : 0;
            kk += (s_bp[kk+ 7] < x) ?  8 : 0;
            kk += (s_bp[kk+ 3] < x) ?  4 : 0;
            kk += (s_bp[kk+ 1] < x) ?  2 : 0;
            kk += (s_bp[kk   ] < x) ?  1 : 0;
            float z = fmaf(s_A[kk], x, s_B[kk]);
            float sg = 1.0f / (1.0f + __expf(-z));
            alpha = sg * 0.98f;

            float dec = __expf(-__fmul_rn(phase, RINV_DEC));
            fn = (n1v[j] * dec) * 0.003f;
        } else {
            fn = n2v[j] * (float)(0.1 / 3.0);
        }
        sigv[j] = sig;
        alv[j]  = alpha;
        fnv[j]  = fn;
    }
    int idx = b*TT + base;
    *(float4*)(g_sig0 + idx)      = *(float4*)&sigv[0];
    *(float4*)(g_sig0 + idx + 4)  = *(float4*)&sigv[4];
    *(float4*)(g_alpha + idx)     = *(float4*)&alv[0];
    *(float4*)(g_alpha + idx + 4) = *(float4*)&alv[4];
    *(float4*)(g_noise + idx)     = *(float4*)&fnv[0];
    *(float4*)(g_noise + idx + 4) = *(float4*)&fnv[4];
}

// ---------------- kernel 3: fused 127-tap conv + IIR scan + last-block carry chain ----------------
__global__ void __launch_bounds__(256) k_convIir(float* __restrict__ out, int out_size){
    __shared__ __align__(16) float s_s[SEG + 136];
    __shared__ __align__(16) float s_ir[128];
    __shared__ float sA[32], sX[32], sPA[32], sPX[32];
    __shared__ int s_last;
    int b = blockIdx.y, seg = blockIdx.x;
    int tid = threadIdx.x, lane = tid & 31, wid = tid >> 5;
    const float* sigb = g_sig0 + b*TT;
    const float* alb  = g_alpha + b*TT;
    float* yb = g_y + b*TT;
    float* pb = g_x + b*TT;
    if (tid < 128) s_ir[tid] = (tid < 127) ? g_ir[tid] : 0.0f;
    int off = seg * SEG;
    for (int j = tid; j < SEG + 136; j += 256){
        int g = off - 63 + j;
        s_s[j] = (g >= 0 && g < TT) ? sigb[g] : 0.0f;
    }
    __syncthreads();
    int o = tid * 8;
    bool valid = (o + 8 <= SEG);     // threads 0..249
    float a0=0.f,a1=0.f,a2=0.f,a3=0.f,a4=0.f,a5=0.f,a6=0.f,a7=0.f;
    float4 aL = make_float4(1.f,1.f,1.f,1.f), aH = aL;
    float4 xL = make_float4(0.f,0.f,0.f,0.f), xH = xL;
    if (valid){
        float4 wva = *(const float4*)&s_s[o];
        float4 wvb = *(const float4*)&s_s[o + 4];
        float w0 = wva.x, w1 = wva.y, w2 = wva.z, w3 = wva.w;
        float w4 = wvb.x, w5 = wvb.y, w6 = wvb.z, w7 = wvb.w;
        #pragma unroll
        for (int k = 0; k < 128; k += 4){
            float4 ir = *(const float4*)&s_ir[k];
            float4 nx = *(const float4*)&s_s[o + k + 8];
            a0=fmaf(w0,ir.x,a0); a1=fmaf(w1,ir.x,a1); a2=fmaf(w2,ir.x,a2); a3=fmaf(w3,ir.x,a3);
            a4=fmaf(w4,ir.x,a4); a5=fmaf(w5,ir.x,a5); a6=fmaf(w6,ir.x,a6); a7=fmaf(w7,ir.x,a7);
            a0=fmaf(w1,ir.y,a0); a1=fmaf(w2,ir.y,a1); a2=fmaf(w3,ir.y,a2); a3=fmaf(w4,ir.y,a3);
            a4=fmaf(w5,ir.y,a4); a5=fmaf(w6,ir.y,a5); a6=fmaf(w7,ir.y,a6); a7=fmaf(nx.x,ir.y,a7);
            a0=fmaf(w2,ir.z,a0); a1=fmaf(w3,ir.z,a1); a2=fmaf(w4,ir.z,a2); a3=fmaf(w5,ir.z,a3);
            a4=fmaf(w6,ir.z,a4); a5=fmaf(w7,ir.z,a5); a6=fmaf(nx.x,ir.z,a6); a7=fmaf(nx.y,ir.z,a7);
            a0=fmaf(w3,ir.w,a0); a1=fmaf(w4,ir.w,a1); a2=fmaf(w5,ir.w,a2); a3=fmaf(w6,ir.w,a3);
            a4=fmaf(w7,ir.w,a4); a5=fmaf(nx.x,ir.w,a5); a6=fmaf(nx.y,ir.w,a6); a7=fmaf(nx.z,ir.w,a7);
            w0=w4; w1=w5; w2=w6; w3=w7;
            w4=nx.x; w5=nx.y; w6=nx.z; w7=nx.w;
        }
        aL = *(const float4*)(alb + off + o);
        aH = *(const float4*)(alb + off + o + 4);
        xL = make_float4((1.0f-aL.x)*a0, (1.0f-aL.y)*a1, (1.0f-aL.z)*a2, (1.0f-aL.w)*a3);
        xH = make_float4((1.0f-aH.x)*a4, (1.0f-aH.y)*a5, (1.0f-aH.z)*a6, (1.0f-aH.w)*a7);
    }
    float A = aL.x, X = xL.x;
    X = fmaf(aL.y, X, xL.y); A = aL.y * A;
    X = fmaf(aL.z, X, xL.z); A = aL.z * A;
    X = fmaf(aL.w, X, xL.w); A = aL.w * A;
    X = fmaf(aH.x, X, xH.x); A = aH.x * A;
    X = fmaf(aH.y, X, xH.y); A = aH.y * A;
    X = fmaf(aH.z, X, xH.z); A = aH.z * A;
    X = fmaf(aH.w, X, xH.w); A = aH.w * A;
    float Ai = A, Xi = X;
    #pragma unroll
    for (int d = 1; d < 32; d <<= 1){
        float ap = __shfl_up_sync(FULLMASK, Ai, d);
        float xp = __shfl_up_sync(FULLMASK, Xi, d);
        if (lane >= d){ Xi = fmaf(Ai, xp, Xi); Ai *= ap; }
    }
    if (lane == 31){ sA[wid] = Ai; sX[wid] = Xi; }
    __syncthreads();
    if (wid == 0){
        float wa2 = sA[lane], wx2 = sX[lane];
        #pragma unroll
        for (int d = 1; d < 32; d <<= 1){
            float ap = __shfl_up_sync(FULLMASK, wa2, d);
            float xp = __shfl_up_sync(FULLMASK, wx2, d);
            if (lane >= d){ wx2 = fmaf(wa2, xp, wx2); wa2 *= ap; }
        }
        sPA[lane] = wa2; sPX[lane] = wx2;
        if (lane == 7){
            g_segA[b*NSEG + seg] = wa2;
            g_segX[b*NSEG + seg] = wx2;
            __threadfence();
        }
    }
    __syncthreads();
    float eA = __shfl_up_sync(FULLMASK, Ai, 1);
    float eX = __shfl_up_sync(FULLMASK, Xi, 1);
    if (lane == 0){ eA = 1.0f; eX = 0.0f; }
    float wA = 1.0f, wX = 0.0f;
    if (wid > 0){ wA = sPA[wid-1]; wX = sPX[wid-1]; }
    float xin = fmaf(eA, wX, eX);
    float Ain = eA * wA;
    float y1 = fmaf(aL.x, xin, xL.x);  float p1 = aL.x * Ain;
    float y2 = fmaf(aL.y, y1, xL.y);   float p2 = aL.y * p1;
    float y3 = fmaf(aL.z, y2, xL.z);   float p3 = aL.z * p2;
    float y4 = fmaf(aL.w, y3, xL.w);   float p4 = aL.w * p3;
    float y5 = fmaf(aH.x, y4, xH.x);   float p5 = aH.x * p4;
    float y6 = fmaf(aH.y, y5, xH.y);   float p6 = aH.y * p5;
    float y7 = fmaf(aH.z, y6, xH.z);   float p7 = aH.z * p6;
    float y8 = fmaf(aH.w, y7, xH.w);   float p8 = aH.w * p7;
    if (valid){
        *(float4*)(yb + off + o)     = make_float4(y1, y2, y3, y4);
        *(float4*)(yb + off + o + 4) = make_float4(y5, y6, y7, y8);
        *(float4*)(pb + off + o)     = make_float4(p1, p2, p3, p4);
        *(float4*)(pb + off + o + 4) = make_float4(p5, p6, p7, p8);
    }
    if (tid == 0){
        __threadfence();
        int old = atomicAdd(&g_done, 1);
        s_last = (old == NB*NSEG - 1) ? 1 : 0;
    }
    __syncthreads();
    if (s_last && tid < NB){
        __threadfence();
        float carry = 0.0f;
        int bb = tid;
        for (int s2 = 0; s2 < NSEG; s2++){
            g_carry[bb*NSEG + s2] = carry;
            carry = fmaf(g_segA[bb*NSEG + s2], carry, g_segX[bb*NSEG + s2]);
        }
        if (out_size >= NB*TT + NB) out[NB*TT + bb] = carry;  // new_state
    }
}

// ---------------- kernel 4: sinc LP/HP FIR + tanh (packed f32x2 taps, imm window) ----------------
__global__ void __launch_bounds__(256) k_fir(const float* __restrict__ cw,
                                             const float* __restrict__ cb,
                                             const float* __restrict__ lw,
                                             float* __restrict__ out){
    __shared__ __align__(8) float2 s_yn[FT + 30];
    __shared__ float s_cr[NSEG];
    int b = blockIdx.y, tb = blockIdx.x * FT, tid = threadIdx.x;
    const float* yb = g_y + b * TT;
    const float* pb = g_x + b * TT;   // Apre
    const float* nb = g_noise + b * TT;
    if (tid >= 64 && tid < 64 + NSEG) s_cr[tid - 64] = g_carry[b*NSEG + (tid - 64)];
    __syncthreads();
    for (int j = tid; j < FT + 30; j += 256){
        int g = tb - 30 + j;
        float yv = 0.0f, nv = 0.0f;
        if (g >= 0 && g < TT){
            int seg = (int)__umulhi((unsigned)g, 2147484u);   // g / 2000, exact for g < 96000
            yv = fmaf(pb[g], s_cr[seg], yb[g]);   // y = y0 + Apre*carry
            nv = nb[g];
        }
        s_yn[j] = make_float2(yv, nv);
    }
    __syncthreads();
    float cw0 = cw[0], cb0 = cb[0], lw0 = lw[0];
    const float PI_F = 3.14159274101257324f;
    #pragma unroll
    for (int r = 0; r < 2; r++){
        int li = tid + r * 256;      // local output index in tile
        int t = tb + li;
        if (t >= TT) continue;
        float f0u = g_f0u[b*TT + t];
        float cz = fmaf(cw0, __fmul_rn(f0u, RINV_NYQ), cb0);
        float cv = __fdividef(1.0f, 1.0f + __expf(-cz));
        float theta = __fmul_rn(PI_F, cv);
        float s1, c1;
        __sincosf(theta, &s1, &c1);      // theta in (0,pi): MUFU accuracy ~1e-6
        float twoc = __fadd_rn(c1, c1);
        float2 cen = s_yn[li + 15];
        u64 cen2 = *(const u64*)&s_yn[li + 15];
        u64 acc = mul2(cen2, pk2(cv, cv));        // lum0 = cv * WM[0] = cv
        float se = 0.0f, so = 0.0f;
        float sm1 = 0.0f, sm = s1;
        #pragma unroll
        for (int m = 1; m < 16; m++){
            float l = __fmul_rn(sm, WMT[m]);      // FMUL with immediate
            if (m & 1) so += l; else se += l;
            u64 um = *(const u64*)&s_yn[li + 15 - m];
            u64 up = *(const u64*)&s_yn[li + 15 + m];
            fma2a(acc, add2(um, up), pk2(l, l));  // both halves correctly rounded
            float sn = fmaf(twoc, sm, -sm1);
            sm1 = sm; sm = sn;
        }
        float accY, accN;
        unpk2(acc, &accY, &accN);
        float suml = cv + 2.0f*(se + so);
        float sumh = (1.0f - cv) - 2.0f*se + 2.0f*so;
        float rl = __fdividef(1.0f, suml + 1e-8f);
        float rh = __fdividef(1.0f, sumh + 1e-8f);
        float e = accY * rl + (cen.y - accN) * rh;   // wm0*cen.y = cen.y
        out[b*TT + t] = tanhf(lw0 * e);
    }
}

// ---------------- launcher ----------------
extern "C" void kernel_launch(void* const* d_in, const int* in_sizes, int n_in,
                              void* d_out, int out_size){
    const float* f0 = (const float*)d_in[0];
    const float* ip = (const float*)d_in[1];
    const float* n1 = (const float*)d_in[2];
    const float* n2 = (const float*)d_in[3];
    const float* w1 = (const float*)d_in[4];
    const float* b1 = (const float*)d_in[5];
    const float* w2 = (const float*)d_in[6];
    const float* b2 = (const float*)d_in[7];
    const float* cw = (const float*)d_in[8];
    const float* cb = (const float*)d_in[9];
    const float* lw = (const float*)d_in[10];
    float* out = (float*)d_out;

    k_setup<<<NB + 2, 256>>>(f0, w1, b1, w2, b2);
    k_phase<<<dim3(NCS, NB), 256>>>(ip, n1, n2);
    k_convIir<<<dim3(NSEG, NB), 256>>>(out, out_size);
    k_fir<<<dim3(NFT, NB), 256>>>(cw, cb, lw, out);
}